// round 2
// baseline (speedup 1.0000x reference)
#include <cuda_runtime.h>
#include <cuda.h>
#include <cuda_bf16.h>
#include <cstdint>
#include <cstddef>

// ---------------- problem dims (fixed) ----------------
#define TT 8192
#define KK 4096
#define NN 4096

#define TILE_M 128
#define TILE_N 128
#define TILE_K 64
#define NCHUNK (KK / TILE_K)      // 64
#define NSTAGE 3

// smem: mbarriers at [0..48), tiles from 1024.
// stage: Ahi 16K | Alo 16K | Bhi 16K | Blo 16K = 65536
#define STAGE_BYTES 65536
#define OFF_TILE 1024
#define SMEM_TOTAL (OFF_TILE + NSTAGE * STAGE_BYTES)   // 197632

// ---------------- scratch (device globals; no allocation allowed) ------
__device__ __nv_bfloat16 g_xhi[(size_t)TT * KK];
__device__ __nv_bfloat16 g_xlo[(size_t)TT * KK];
__device__ __nv_bfloat16 g_whi[(size_t)NN * KK];
__device__ __nv_bfloat16 g_wlo[(size_t)NN * KK];

// ---------------- PTX helpers (non-'a' baseline only) -------------------
__device__ __forceinline__ uint32_t smem_u32(const void* p) {
    uint32_t a;
    asm("{ .reg .u64 t; cvta.to.shared.u64 t, %1; cvt.u32.u64 %0, t; }"
        : "=r"(a) : "l"(p));
    return a;
}

__device__ __forceinline__ void mbar_init(uint32_t addr, uint32_t count) {
    asm volatile("mbarrier.init.shared.b64 [%0], %1;" :: "r"(addr), "r"(count) : "memory");
}

__device__ __forceinline__ void mbar_expect_tx(uint32_t addr, uint32_t bytes) {
    asm volatile("mbarrier.arrive.expect_tx.shared.b64 _, [%0], %1;"
                 :: "r"(addr), "r"(bytes) : "memory");
}

__device__ __forceinline__ void mbar_wait(uint32_t addr, uint32_t parity) {
    asm volatile(
        "{\n\t"
        ".reg .pred P;\n\t"
        "LAB_WAIT_%=:\n\t"
        "mbarrier.try_wait.parity.acquire.cta.shared::cta.b64 P, [%0], %1, 0x989680;\n\t"
        "@P bra LAB_DONE_%=;\n\t"
        "bra LAB_WAIT_%=;\n\t"
        "LAB_DONE_%=:\n\t"
        "}"
        :: "r"(addr), "r"(parity) : "memory");
}

__device__ __forceinline__ void tma_load3(uint32_t dst, const CUtensorMap* map,
                                          int cx, int cy, uint32_t mbar) {
    asm volatile(
        "cp.async.bulk.tensor.3d.shared::cta.global.tile.mbarrier::complete_tx::bytes "
        "[%0], [%1, {%2, %3, %4}], [%5];"
        :: "r"(dst), "l"(map), "r"(cx), "r"(cy), "r"(0), "r"(mbar)
        : "memory");
}

__device__ __forceinline__ void ldsm4(uint32_t* r, uint32_t addr) {
    asm volatile("ldmatrix.sync.aligned.m8n8.x4.shared.b16 {%0,%1,%2,%3}, [%4];"
                 : "=r"(r[0]), "=r"(r[1]), "=r"(r[2]), "=r"(r[3]) : "r"(addr));
}

__device__ __forceinline__ void mma_bf16(float* c, const uint32_t* a,
                                         uint32_t b0, uint32_t b1) {
    asm volatile(
        "mma.sync.aligned.m16n8k16.row.col.f32.bf16.bf16.f32 "
        "{%0,%1,%2,%3}, {%4,%5,%6,%7}, {%8,%9}, {%0,%1,%2,%3};"
        : "+f"(c[0]), "+f"(c[1]), "+f"(c[2]), "+f"(c[3])
        : "r"(a[0]), "r"(a[1]), "r"(a[2]), "r"(a[3]), "r"(b0), "r"(b1));
}

// ---------------- prep kernels ------------------------------------------
// act_quant round-trip is exact to fp32 rounding -> skip it; just split
// fp32 into bf16 hi + bf16 lo (residual).
__global__ void prep_x_kernel(const float4* __restrict__ x,
                              __nv_bfloat162* __restrict__ hi,
                              __nv_bfloat162* __restrict__ lo, int n4) {
    int i = blockIdx.x * blockDim.x + threadIdx.x;
    if (i >= n4) return;
    float4 v = x[i];
    float a[4] = {v.x, v.y, v.z, v.w};
    __nv_bfloat16 h[4], l[4];
#pragma unroll
    for (int j = 0; j < 4; j++) {
        h[j] = __float2bfloat16_rn(a[j]);
        l[j] = __float2bfloat16_rn(a[j] - __bfloat162float(h[j]));
    }
    __nv_bfloat162 t;
    t.x = h[0]; t.y = h[1]; hi[2 * i]     = t;
    t.x = h[2]; t.y = h[3]; hi[2 * i + 1] = t;
    t.x = l[0]; t.y = l[1]; lo[2 * i]     = t;
    t.x = l[2]; t.y = l[3]; lo[2 * i + 1] = t;
}

// Dequant weight (per 128x128 block scale) then split hi/lo.
__global__ void prep_w_kernel(const float4* __restrict__ wq,
                              const float* __restrict__ ws,
                              __nv_bfloat162* __restrict__ hi,
                              __nv_bfloat162* __restrict__ lo, int n4) {
    int i = blockIdx.x * blockDim.x + threadIdx.x;
    if (i >= n4) return;
    int e0 = i << 2;                  // element index
    int n = e0 >> 12;                 // / 4096 (K)
    int k = e0 & 4095;
    float s = ws[(n >> 7) * (KK / 128) + (k >> 7)];
    float4 v = wq[i];
    float a[4] = {v.x * s, v.y * s, v.z * s, v.w * s};
    __nv_bfloat16 h[4], l[4];
#pragma unroll
    for (int j = 0; j < 4; j++) {
        h[j] = __float2bfloat16_rn(a[j]);
        l[j] = __float2bfloat16_rn(a[j] - __bfloat162float(h[j]));
    }
    __nv_bfloat162 t;
    t.x = h[0]; t.y = h[1]; hi[2 * i]     = t;
    t.x = h[2]; t.y = h[3]; hi[2 * i + 1] = t;
    t.x = l[0]; t.y = l[1]; lo[2 * i]     = t;
    t.x = l[2]; t.y = l[3]; lo[2 * i + 1] = t;
}

// ---------------- GEMM kernel --------------------------------------------
// CTA 128x128, 256 threads, 8 warps in 2(M) x 4(N); warp tile 64x32.
// 3-stage TMA pipeline; bf16x3 passes: hi*hi + hi*lo + lo*hi.

__device__ __forceinline__ void issue_chunk(uint32_t sb, int c, int m0, int n0,
                                            const CUtensorMap* pah,
                                            const CUtensorMap* pal,
                                            const CUtensorMap* pbh,
                                            const CUtensorMap* pbl) {
    int st = c % NSTAGE;
    uint32_t mb = sb + 16 * st;
    mbar_expect_tx(mb, (uint32_t)STAGE_BYTES);
    int k0 = c * TILE_K;
    uint32_t base = sb + OFF_TILE + st * STAGE_BYTES;
    tma_load3(base,         pah, k0, m0, mb);
    tma_load3(base + 16384, pal, k0, m0, mb);
    tma_load3(base + 32768, pbh, k0, n0, mb);
    tma_load3(base + 49152, pbl, k0, n0, mb);
}

__global__ void __launch_bounds__(256, 1)
gemm_kernel(const __grid_constant__ CUtensorMap map_ahi,
            const __grid_constant__ CUtensorMap map_alo,
            const __grid_constant__ CUtensorMap map_bhi,
            const __grid_constant__ CUtensorMap map_blo,
            const float* __restrict__ bias,
            float* __restrict__ out) {
    extern __shared__ char smem[];
    uint32_t sb = smem_u32(smem);
    int tid = threadIdx.x;
    int l = tid & 31, wid = tid >> 5;
    int wm = wid >> 2, wn = wid & 3;        // 2 x 4 warp grid
    int m0 = blockIdx.y * TILE_M;
    int n0 = blockIdx.x * TILE_N;

    if (tid == 0) {
        for (int s = 0; s < NSTAGE; s++) mbar_init(sb + 16 * s, 1);
        asm volatile("fence.proxy.async.shared::cta;" ::: "memory");
    }
    __syncthreads();

    if (tid == 0) {
        issue_chunk(sb, 0, m0, n0, &map_ahi, &map_alo, &map_bhi, &map_blo);
        issue_chunk(sb, 1, m0, n0, &map_ahi, &map_alo, &map_bhi, &map_blo);
    }

    // lane constants for swizzled ldmatrix addressing
    int lm = l & 15;
    int lh = (l >> 4) << 4;                 // 0 or 16 bytes (k half)
    uint32_t xorv = (uint32_t)(lm & 7) << 4;
    uint32_t arow[4], brow[2];
#pragma unroll
    for (int mt = 0; mt < 4; mt++) arow[mt] = (uint32_t)(wm * 64 + mt * 16 + lm) * 128;
#pragma unroll
    for (int bt = 0; bt < 2; bt++) brow[bt] = (uint32_t)(wn * 32 + bt * 16 + lm) * 128;

    float acc[4][4][4] = {};

    for (int c = 0; c < NCHUNK; c++) {
        int st = c % NSTAGE;
        uint32_t ph = (uint32_t)((c / NSTAGE) & 1);
        mbar_wait(sb + 16 * st, ph);

        uint32_t stA = sb + OFF_TILE + st * STAGE_BYTES;
        uint32_t stAl = stA + 16384, stB = stA + 32768, stBl = stA + 49152;

#pragma unroll
        for (int ks = 0; ks < TILE_K / 16; ks++) {
            uint32_t lob = ((uint32_t)(lh + ks * 32)) ^ xorv;
            uint32_t ah[4][4], al[4][4], bh[2][4], bl[2][4];
#pragma unroll
            for (int mt = 0; mt < 4; mt++) ldsm4(ah[mt], stA  + arow[mt] + lob);
#pragma unroll
            for (int mt = 0; mt < 4; mt++) ldsm4(al[mt], stAl + arow[mt] + lob);
#pragma unroll
            for (int bt = 0; bt < 2; bt++) ldsm4(bh[bt], stB  + brow[bt] + lob);
#pragma unroll
            for (int bt = 0; bt < 2; bt++) ldsm4(bl[bt], stBl + brow[bt] + lob);

#pragma unroll
            for (int mt = 0; mt < 4; mt++) {
#pragma unroll
                for (int nt = 0; nt < 4; nt++) {
                    int bt = nt >> 1, se = nt & 1;
                    mma_bf16(acc[mt][nt], ah[mt], bh[bt][se], bh[bt][se + 2]);
                    mma_bf16(acc[mt][nt], ah[mt], bl[bt][se], bl[bt][se + 2]);
                    mma_bf16(acc[mt][nt], al[mt], bh[bt][se], bh[bt][se + 2]);
                }
            }
        }
        __syncthreads();
        if (tid == 0 && c + 2 < NCHUNK) {
            issue_chunk(sb, c + 2, m0, n0, &map_ahi, &map_alo, &map_bhi, &map_blo);
        }
    }

    // epilogue: bias add + fp32 stores (float2 pairs, mma C-frag layout)
    int g = l >> 2;                // group row within m8
    int q = (l & 3) * 2;           // col pair within n8
#pragma unroll
    for (int mt = 0; mt < 4; mt++) {
        int r0 = m0 + wm * 64 + mt * 16 + g;
#pragma unroll
        for (int nt = 0; nt < 4; nt++) {
            int col = n0 + wn * 32 + nt * 8 + q;
            float2 bv = *reinterpret_cast<const float2*>(bias + col);
            float2 v0, v1;
            v0.x = acc[mt][nt][0] + bv.x;
            v0.y = acc[mt][nt][1] + bv.y;
            v1.x = acc[mt][nt][2] + bv.x;
            v1.y = acc[mt][nt][3] + bv.y;
            *reinterpret_cast<float2*>(out + (size_t)r0 * NN + col) = v0;
            *reinterpret_cast<float2*>(out + (size_t)(r0 + 8) * NN + col) = v1;
        }
    }
}

// ---------------- host launch ---------------------------------------------
typedef CUresult (*PFN_encodeTiled)(CUtensorMap*, CUtensorMapDataType, cuuint32_t,
                                    void*, const cuuint64_t*, const cuuint64_t*,
                                    const cuuint32_t*, const cuuint32_t*,
                                    CUtensorMapInterleave, CUtensorMapSwizzle,
                                    CUtensorMapL2promotion, CUtensorMapFloatOOBfill);

static void encode_map(PFN_encodeTiled enc, CUtensorMap* m, void* ptr,
                       unsigned long long d0, unsigned long long d1,
                       unsigned b0, unsigned b1) {
    cuuint64_t dims[3]    = {d0, d1, 1};
    cuuint64_t strides[2] = {d0 * 2ull, d0 * d1 * 2ull};   // bf16
    cuuint32_t box[3]     = {b0, b1, 1};
    cuuint32_t es[3]      = {1, 1, 1};
    enc(m, CU_TENSOR_MAP_DATA_TYPE_BFLOAT16, 3, ptr, dims, strides, box, es,
        CU_TENSOR_MAP_INTERLEAVE_NONE, CU_TENSOR_MAP_SWIZZLE_128B,
        CU_TENSOR_MAP_L2_PROMOTION_L2_128B, CU_TENSOR_MAP_FLOAT_OOB_FILL_NONE);
}

extern "C" void kernel_launch(void* const* d_in, const int* in_sizes, int n_in,
                              void* d_out, int out_size) {
    const float* x    = (const float*)d_in[0];
    const float* wq   = (const float*)d_in[1];
    const float* ws   = (const float*)d_in[2];
    const float* bias = (const float*)d_in[3];
    float* out = (float*)d_out;

    void *pxhi, *pxlo, *pwhi, *pwlo;
    cudaGetSymbolAddress(&pxhi, g_xhi);
    cudaGetSymbolAddress(&pxlo, g_xlo);
    cudaGetSymbolAddress(&pwhi, g_whi);
    cudaGetSymbolAddress(&pwlo, g_wlo);

    int n4x = TT * (KK / 4);
    prep_x_kernel<<<n4x / 256, 256>>>((const float4*)x,
                                      (__nv_bfloat162*)pxhi, (__nv_bfloat162*)pxlo, n4x);
    int n4w = NN * (KK / 4);
    prep_w_kernel<<<n4w / 256, 256>>>((const float4*)wq, ws,
                                      (__nv_bfloat162*)pwhi, (__nv_bfloat162*)pwlo, n4w);

    void* fn = nullptr;
    cudaDriverEntryPointQueryResult qr;
    cudaGetDriverEntryPointByVersion("cuTensorMapEncodeTiled", &fn, 12000,
                                     cudaEnableDefault, &qr);
    PFN_encodeTiled enc = (PFN_encodeTiled)fn;

    CUtensorMap mahi, malo, mbhi, mblo;
    encode_map(enc, &mahi, pxhi, KK, TT, TILE_K, TILE_M);
    encode_map(enc, &malo, pxlo, KK, TT, TILE_K, TILE_M);
    encode_map(enc, &mbhi, pwhi, KK, NN, TILE_K, TILE_N);
    encode_map(enc, &mblo, pwlo, KK, NN, TILE_K, TILE_N);

    cudaFuncSetAttribute(gemm_kernel, cudaFuncAttributeMaxDynamicSharedMemorySize,
                         SMEM_TOTAL);
    dim3 grid(NN / TILE_N, TT / TILE_M);   // 32 x 64
    gemm_kernel<<<grid, 256, SMEM_TOTAL>>>(mahi, malo, mbhi, mblo, bias, out);
}